// round 5
// baseline (speedup 1.0000x reference)
#include <cuda_runtime.h>
#include <cuda_bf16.h>

typedef unsigned long long u64;

// Cross-block scratch (no allocations allowed -> __device__ globals)
__device__ float2 g_v[4][4096];   // 4 columns of the circuit unitary (natural order)
__device__ int g_flag = 0;        // sim-columns-done counter (self-resetting)
__device__ int g_done2 = 0;       // output-blocks-passed-spin counter

// ---------------- f32x2 packed helpers ----------------
__device__ __forceinline__ u64 pack2(float x, float y) {
    u64 u; asm("mov.b64 %0, {%1,%2};" : "=l"(u) : "f"(x), "f"(y)); return u;
}
__device__ __forceinline__ float2 unpack2(u64 u) {
    float2 v; asm("mov.b64 {%0,%1}, %2;" : "=f"(v.x), "=f"(v.y) : "l"(u)); return v;
}
__device__ __forceinline__ u64 swap2(u64 u) {
    float2 v = unpack2(u); return pack2(v.y, v.x);
}
__device__ __forceinline__ u64 fma2(u64 a, u64 b, u64 c) {
    u64 d; asm("fma.rn.f32x2 %0, %1, %2, %3;" : "=l"(d) : "l"(a), "l"(b), "l"(c)); return d;
}
__device__ __forceinline__ u64 mul2(u64 a, u64 b) {
    u64 d; asm("mul.rn.f32x2 %0, %1, %2;" : "=l"(d) : "l"(a), "l"(b)); return d;
}

// Packed per-lane gate coefficients: self (s) and off-diagonal (o) complex coeffs
struct Coef { u64 sx, sy, nsy, ox, oy, noy; };

__device__ __forceinline__ Coef makeCoef(float2 s0, float2 o0, float2 s1, float2 o1) {
    Coef c;
    c.sx  = pack2(s0.x, s1.x);
    c.sy  = pack2(s0.y, s1.y);
    c.nsy = pack2(-s0.y, -s1.y);
    c.ox  = pack2(o0.x, o1.x);
    c.oy  = pack2(o0.y, o1.y);
    c.noy = pack2(-o0.y, -o1.y);
    return c;
}

// new = s*a + o*p (complex, 2 lanes): 8 f32x2 ops
__device__ __forceinline__ void cupd(u64 X, u64 Y, u64 PX, u64 PY, const Coef& c,
                                     u64& NX, u64& NY) {
    u64 nx = mul2(c.sx, X);
    nx = fma2(c.nsy, Y, nx);
    nx = fma2(c.ox, PX, nx);
    nx = fma2(c.noy, PY, nx);
    u64 ny = mul2(c.sx, Y);
    ny = fma2(c.sy, X, ny);
    ny = fma2(c.ox, PY, ny);
    ny = fma2(c.oy, PX, ny);
    NX = nx; NY = ny;
}

// ---------------- shared memory (dynamic, 67KB) ----------------
struct SimSmem {
    float2 rot[96][4];            // u00,u01,u10,u11 per gate
    u64 bAX[2048]; u64 bAY[2048]; // staging buffer A (phase 2)
    u64 bBX[2048]; u64 bBY[2048]; // staging buffer B (phase 3)
};

// physical float slot of amplitude index x in the [pair-hi][thread][lane]
// staging layout:  float addr = ((x&6)<<9) | ((x>>3)<<1) | (x&1)
__device__ __forceinline__ int physf(int x) {
    return ((x & 6) << 9) | ((x >> 3) << 1) | (x & 1);
}
// sigma: swap index bits {0..3} <-> {8..11} (involution)
__device__ __forceinline__ int sigma(int s) {
    return (s & 0x0F0) | ((s & 0xF) << 8) | ((s >> 8) & 0xF);
}

// ---------------------------------------------------------------------------
// Gates. State: 8 amplitudes/thread as 4 lane-pairs: AX[i]=(re(2i),re(2i+1)),
// AY[i]=(im(2i),im(2i+1)). Storage index x = (t<<3) | l (t: 9 bits, l: 3 bits).
// ---------------------------------------------------------------------------

// gate at bit 0: partner = other lane of same pair
__device__ __forceinline__ void gate_p0(u64 AX[4], u64 AY[4], const float2* u) {
    Coef C = makeCoef(u[0], u[1], u[3], u[2]);
    #pragma unroll
    for (int i = 0; i < 4; i++) {
        u64 px = swap2(AX[i]), py = swap2(AY[i]);
        cupd(AX[i], AY[i], px, py, C, AX[i], AY[i]);
    }
}

// gate at bit 1 (HS=1) or bit 2 (HS=2): partner pair = i ^ HS
template<int HS>
__device__ __forceinline__ void gate_reg(u64 AX[4], u64 AY[4], const float2* u) {
    Coef C0 = makeCoef(u[0], u[1], u[0], u[1]);
    Coef C1 = makeCoef(u[3], u[2], u[3], u[2]);
    #pragma unroll
    for (int a = 0; a < 4; a++) {
        if (a & HS) continue;
        int b = a | HS;
        u64 nx0, ny0, nx1, ny1;
        cupd(AX[a], AY[a], AX[b], AY[b], C0, nx0, ny0);
        cupd(AX[b], AY[b], AX[a], AY[a], C1, nx1, ny1);
        AX[a] = nx0; AY[a] = ny0; AX[b] = nx1; AY[b] = ny1;
    }
}

// gate at bit P in 3..7: partner in lane t ^ (1<<(P-3)); branch = that bit of t
template<int P>
__device__ __forceinline__ void gate_lane(u64 AX[4], u64 AY[4], const float2* u, int t) {
    const int lm = 1 << (P - 3);
    const bool pt = (t >> (P - 3)) & 1;
    float2 s = pt ? u[3] : u[0];
    float2 o = pt ? u[2] : u[1];
    Coef C = makeCoef(s, o, s, o);
    #pragma unroll
    for (int i = 0; i < 4; i++) {
        float2 ax = unpack2(AX[i]), ay = unpack2(AY[i]);
        ax.x = __shfl_xor_sync(0xffffffffu, ax.x, lm);
        ax.y = __shfl_xor_sync(0xffffffffu, ax.y, lm);
        ay.x = __shfl_xor_sync(0xffffffffu, ay.x, lm);
        ay.y = __shfl_xor_sync(0xffffffffu, ay.y, lm);
        cupd(AX[i], AY[i], pack2(ax.x, ax.y), pack2(ay.x, ay.y), C, AX[i], AY[i]);
    }
}

// ---------------------------------------------------------------------------
// Fused kernel. Blocks 0..3: simulate one basis column each (512 thr, 8 amps).
// Blocks 4..: wait for columns, build 4x4 Gram, emit 512 outputs each.
// ---------------------------------------------------------------------------
__global__ __launch_bounds__(512, 1) void fused_kernel(
    const float* __restrict__ weights, const float* __restrict__ head_w,
    const float* __restrict__ head_b, const float* __restrict__ sb,
    float* __restrict__ out, int B, int nOut)
{
    extern __shared__ char smem_raw[];
    const int t = threadIdx.x;
    const int bid = blockIdx.x;

    if (bid < 4) {
        // ================= SIM BLOCK =================
        SimSmem* sm = (SimSmem*)smem_raw;
        if (t < 96) {
            float phi = weights[t * 3 + 0];
            float th  = weights[t * 3 + 1];
            float om  = weights[t * 3 + 2];
            float st, ct; sincosf(th * 0.5f, &st, &ct);
            float sp, cp; sincosf((phi + om) * 0.5f, &sp, &cp);
            float sd, cd; sincosf((phi - om) * 0.5f, &sd, &cd);
            sm->rot[t][0] = make_float2( cp * ct, -sp * ct);   // u00
            sm->rot[t][1] = make_float2(-cd * st, -sd * st);   // u01
            sm->rot[t][2] = make_float2( cd * st, -sd * st);   // u10
            sm->rot[t][3] = make_float2( cp * ct,  sp * ct);   // u11
        }
        __syncthreads();

        // init |kj>: kj = b0*2048 + b1*1024 -> thread kj>>3, local 0
        const int t_init = ((bid >> 1) & 1) * 256 + (bid & 1) * 128;
        u64 AX[4], AY[4];
        #pragma unroll
        for (int i = 0; i < 4; i++) { AX[i] = 0ull; AY[i] = 0ull; }
        if (t == t_init) AX[0] = pack2(1.0f, 0.0f);

        // Precompute layer-invariant read addresses (float slots).
        // phase2: A_z[z] = staged[sigma(z)], z = (t<<3)|(p<<1)|lam
        //   full addr = physf(sigma(t<<3)) + lam*64 + p*128
        //   sigma(t<<3) = [bits0..3 = t5..t8 | bits4..7 = t1..t4 | bit11 = t0]
        //   -> physf contributions: bits0..7 part = xb below; bit11 (t0) lands
        //      at float bit 9 (= +512), which xb cannot carry. Add it explicitly.
        const int xb = ((t >> 5) & 0xF) | (((t >> 1) & 0xF) << 4);
        const int a2 = physf(xb) + (t & 1) * 512;   // <-- R4 bugfix: +t0*512
        // phase3: A'[y] = staged[sigma(y ^ (y>>1))]
        int a3[4][2];
        #pragma unroll
        for (int p = 0; p < 4; p++)
            #pragma unroll
            for (int lam = 0; lam < 2; lam++) {
                int y = (t << 3) | (p << 1) | lam;
                int s = (y ^ (y >> 1)) & 0xFFF;
                a3[p][lam] = physf(sigma(s));
            }
        float* fAX = (float*)sm->bAX; float* fAY = (float*)sm->bAY;
        float* fBX = (float*)sm->bBX; float* fBY = (float*)sm->bBY;

        #pragma unroll 1
        for (int l = 0; l < 8; l++) {
            const float2 (*R)[4] = (const float2 (*)[4]) & sm->rot[l * 12];
            // ---- phase 1: wires 11..4 at bits 0..7 (reg/shfl only) ----
            gate_p0(AX, AY, R[11]);
            gate_reg<1>(AX, AY, R[10]);
            gate_reg<2>(AX, AY, R[9]);
            gate_lane<3>(AX, AY, R[8], t);
            gate_lane<4>(AX, AY, R[7], t);
            gate_lane<5>(AX, AY, R[6], t);
            gate_lane<6>(AX, AY, R[5], t);
            gate_lane<7>(AX, AY, R[4], t);
            // ---- phase 2: transpose (swap bits 0..3 <-> 8..11) via bufA ----
            #pragma unroll
            for (int i = 0; i < 4; i++) {
                sm->bAX[(i << 9) | t] = AX[i];
                sm->bAY[(i << 9) | t] = AY[i];
            }
            __syncthreads();
            #pragma unroll
            for (int p = 0; p < 4; p++) {
                AX[p] = pack2(fAX[a2 + p * 128], fAX[a2 + p * 128 + 64]);
                AY[p] = pack2(fAY[a2 + p * 128], fAY[a2 + p * 128 + 64]);
            }
            // wires 3,2,1,0 now at z-bits 0,1,2,3
            gate_p0(AX, AY, R[3]);
            gate_reg<1>(AX, AY, R[2]);
            gate_reg<2>(AX, AY, R[1]);
            gate_lane<3>(AX, AY, R[0], t);
            // ---- phase 3: un-transpose + CNOT perm fused via bufB ----
            #pragma unroll
            for (int i = 0; i < 4; i++) {
                sm->bBX[(i << 9) | t] = AX[i];
                sm->bBY[(i << 9) | t] = AY[i];
            }
            __syncthreads();
            #pragma unroll
            for (int p = 0; p < 4; p++) {
                AX[p] = pack2(fBX[a3[p][0]], fBX[a3[p][1]]);
                AY[p] = pack2(fBY[a3[p][0]], fBY[a3[p][1]]);
            }
        }

        // write column (natural order)
        #pragma unroll
        for (int i = 0; i < 4; i++) {
            float2 xs = unpack2(AX[i]), ys = unpack2(AY[i]);
            g_v[bid][(t << 3) | (2 * i)]     = make_float2(xs.x, ys.x);
            g_v[bid][(t << 3) | (2 * i + 1)] = make_float2(xs.y, ys.y);
        }
        __threadfence();
        __syncthreads();
        if (t == 0) atomicAdd(&g_flag, 1);
    } else {
        // ================= OUTPUT BLOCK =================
        if (t == 0) {
            while (atomicAdd(&g_flag, 0) < 4) __nanosleep(64);
        }
        __syncthreads();
        __threadfence();

        // --- Gram: G[j][k] = sum_idx s(idx) v_j conj(v_k) ---
        float hw[12];
        #pragma unroll
        for (int w = 0; w < 12; w++) hw[w] = head_w[w];

        float2 acc[4][4];
        #pragma unroll
        for (int a = 0; a < 4; a++)
            #pragma unroll
            for (int b = 0; b < 4; b++) acc[a][b] = make_float2(0.f, 0.f);

        for (int idx = t; idx < 4096; idx += 512) {
            float s = 0.f;
            #pragma unroll
            for (int w = 0; w < 12; w++)
                s += ((idx >> (11 - w)) & 1) ? -hw[w] : hw[w];
            float2 v[4];
            #pragma unroll
            for (int a = 0; a < 4; a++) v[a] = g_v[a][idx];
            #pragma unroll
            for (int a = 0; a < 4; a++)
                #pragma unroll
                for (int b = 0; b < 4; b++) {
                    float pr = v[a].x * v[b].x + v[a].y * v[b].y;
                    float pi = v[a].y * v[b].x - v[a].x * v[b].y;
                    acc[a][b].x += s * pr;
                    acc[a][b].y += s * pi;
                }
        }

        float* red = (float*)smem_raw;      // [16][32]
        float* Gs  = red + 16 * 32;         // [32]
        float* flat = reinterpret_cast<float*>(acc);
        const int lane = t & 31, warp = t >> 5;
        #pragma unroll
        for (int comp = 0; comp < 32; comp++) {
            float v = flat[comp];
            #pragma unroll
            for (int off = 16; off; off >>= 1)
                v += __shfl_down_sync(0xffffffff, v, off);
            if (lane == 0) red[warp * 32 + comp] = v;
        }
        __syncthreads();
        if (t < 32) {
            float v = 0.f;
            #pragma unroll
            for (int w = 0; w < 16; w++) v += red[w * 32 + t];
            Gs[t] = v;
        }
        __syncthreads();

        // self-resetting flags for graph replays (all blocks passed the spin)
        if (t == 0) {
            int d = atomicAdd(&g_done2, 1);
            if (d == nOut - 1) { atomicExch(&g_flag, 0); atomicExch(&g_done2, 0); }
        }

        // --- per-sample output: out = Re(c^H G c) + bias ---
        int i = (bid - 4) * 512 + t;
        if (i < B) {
            float t0 = sb[i * 8 + 0], t1 = sb[i * 8 + 1];
            float s0, c0, s1, c1;
            sincosf(t0 * 0.5f, &s0, &c0);
            sincosf(t1 * 0.5f, &s1, &c1);
            float2 c[4];
            c[0] = make_float2(c0 * c1, 0.f);
            c[1] = make_float2(c0 * s1, 0.f);
            c[2] = make_float2(0.f, -s0 * c1);
            c[3] = make_float2(0.f, -s0 * s1);

            float res = head_b[0];
            #pragma unroll
            for (int jj = 0; jj < 4; jj++)
                #pragma unroll
                for (int k = 0; k < 4; k++) {
                    float ccr = c[jj].x * c[k].x + c[jj].y * c[k].y;
                    float cci = c[jj].y * c[k].x - c[jj].x * c[k].y;
                    float gx = Gs[(jj * 4 + k) * 2];
                    float gy = Gs[(jj * 4 + k) * 2 + 1];
                    res += ccr * gx - cci * gy;
                }
            out[i] = res;
        }
    }
}

extern "C" void kernel_launch(void* const* d_in, const int* in_sizes, int n_in,
                              void* d_out, int out_size) {
    const float* state_batch = (const float*)d_in[0];  // (B, 8)
    const float* weights     = (const float*)d_in[1];  // (8, 12, 3)
    const float* head_w      = (const float*)d_in[2];  // (1, 12)
    const float* head_b      = (const float*)d_in[3];  // (1,)
    float* out = (float*)d_out;
    const int B = in_sizes[0] / 8;

    const int smem_bytes = (int)sizeof(SimSmem);
    cudaFuncSetAttribute(fused_kernel, cudaFuncAttributeMaxDynamicSharedMemorySize,
                         smem_bytes);
    const int nOut = (B + 511) / 512;
    fused_kernel<<<4 + nOut, 512, smem_bytes>>>(weights, head_w, head_b,
                                                state_batch, out, B, nOut);
}

// round 6
// speedup vs baseline: 1.1159x; 1.1159x over previous
#include <cuda_runtime.h>
#include <cuda_bf16.h>

typedef unsigned long long u64;

// Cross-block scratch (no allocations allowed -> __device__ globals)
__device__ float2 g_v[4][4096];   // 4 columns of the circuit unitary (natural order)
__device__ int g_flag = 0;        // sim-columns-done counter (self-resetting)
__device__ int g_done2 = 0;       // output-blocks-passed-spin counter

// ---------------- f32x2 packed helpers ----------------
__device__ __forceinline__ u64 pack2(float x, float y) {
    u64 u; asm("mov.b64 %0, {%1,%2};" : "=l"(u) : "f"(x), "f"(y)); return u;
}
__device__ __forceinline__ float2 unpack2(u64 u) {
    float2 v; asm("mov.b64 {%0,%1}, %2;" : "=f"(v.x), "=f"(v.y) : "l"(u)); return v;
}
__device__ __forceinline__ u64 swap2(u64 u) {
    float2 v = unpack2(u); return pack2(v.y, v.x);
}
__device__ __forceinline__ u64 fma2(u64 a, u64 b, u64 c) {
    u64 d; asm("fma.rn.f32x2 %0, %1, %2, %3;" : "=l"(d) : "l"(a), "l"(b), "l"(c)); return d;
}
__device__ __forceinline__ u64 mul2(u64 a, u64 b) {
    u64 d; asm("mul.rn.f32x2 %0, %1, %2;" : "=l"(d) : "l"(a), "l"(b)); return d;
}

// Packed per-lane gate coefficients: self (s) and off-diagonal (o) complex coeffs
struct Coef { u64 sx, sy, nsy, ox, oy, noy; };

__device__ __forceinline__ Coef makeCoef(float2 s0, float2 o0, float2 s1, float2 o1) {
    Coef c;
    c.sx  = pack2(s0.x, s1.x);
    c.sy  = pack2(s0.y, s1.y);
    c.nsy = pack2(-s0.y, -s1.y);
    c.ox  = pack2(o0.x, o1.x);
    c.oy  = pack2(o0.y, o1.y);
    c.noy = pack2(-o0.y, -o1.y);
    return c;
}

// new = s*a + o*p (complex, 2 packed lanes): 8 f32x2 ops
__device__ __forceinline__ void cupd(u64 X, u64 Y, u64 PX, u64 PY, const Coef& c,
                                     u64& NX, u64& NY) {
    u64 nx = mul2(c.sx, X);
    nx = fma2(c.nsy, Y, nx);
    nx = fma2(c.ox, PX, nx);
    nx = fma2(c.noy, PY, nx);
    u64 ny = mul2(c.sx, Y);
    ny = fma2(c.sy, X, ny);
    ny = fma2(c.ox, PY, ny);
    ny = fma2(c.oy, PX, ny);
    NX = nx; NY = ny;
}

// ---------------- shared memory (dynamic, ~67KB) ----------------
struct SimSmem {
    float2 rot[96][4];              // u00,u01,u10,u11 per gate
    u64 aX[2048]; u64 aY[2048];     // staging A (transpose)
    u64 bX[2048]; u64 bY[2048];     // staging B (untranspose + CNOT perm)
};

// ---------------------------------------------------------------------------
// Indexing. 256 threads (t: t0..t4 lane, t5..t7 warp), 16 amps/thread.
// Amp index x (12 bits): x0..x2 = pair index p, x3 = pack lane (u64),
// x4..x8 = lane bits t0..t4, x9..x11 = warp bits t5..t7.
// Wire w acts on bit 11-w.
// Transpose sigma swaps bits {0,1,2} <-> {9,10,11} ONLY (pack + lane fixed).
// Staging slot for pair of amp x: slot = (x0x1x2)<<8 | (x4..x11); float = 2*slot + x3.
// ---------------------------------------------------------------------------

// float address in staging buffer of FINAL amp y, after untranspose+CNOT perm:
// source natural amp = y ^ (y>>1); its staged position = sigma of that.
__host__ __device__ constexpr int addr3(int y) {
    int g = (y ^ (y >> 1)) & 0xFFF;
    int z = (g & 0x1F8) | ((g & 7) << 9) | ((g >> 9) & 7);   // sigma(g)
    int slot = ((z & 7) << 8) | ((z >> 4) & 0xFF);
    return (slot << 1) | ((z >> 3) & 1);
}

// gate on a pair-index bit M (in-register partner A[p^M])
template<int M>
__device__ __forceinline__ void gate_regM(u64 AX[8], u64 AY[8], const float2* u) {
    Coef C0 = makeCoef(u[0], u[1], u[0], u[1]);
    Coef C1 = makeCoef(u[3], u[2], u[3], u[2]);
    #pragma unroll
    for (int p = 0; p < 8; p++) {
        if (p & M) continue;
        int q = p | M;
        u64 x0 = AX[p], y0 = AY[p], x1 = AX[q], y1 = AY[q];
        cupd(x0, y0, x1, y1, C0, AX[p], AY[p]);
        cupd(x1, y1, x0, y0, C1, AX[q], AY[q]);
    }
}

// gate on the pack bit (partner = other f32x2 lane)
__device__ __forceinline__ void gate_pack(u64 AX[8], u64 AY[8], const float2* u) {
    Coef C = makeCoef(u[0], u[1], u[3], u[2]);
    #pragma unroll
    for (int p = 0; p < 8; p++) {
        u64 px = swap2(AX[p]), py = swap2(AY[p]);
        cupd(AX[p], AY[p], px, py, C, AX[p], AY[p]);
    }
}

// gate on lane bit K (shfl partner lane t ^ LM, LM = 1<<K)
template<int LM, int K>
__device__ __forceinline__ void gate_lane(u64 AX[8], u64 AY[8], const float2* u, int t) {
    const bool pt = (t >> K) & 1;
    float2 s = pt ? u[3] : u[0];
    float2 o = pt ? u[2] : u[1];
    Coef C = makeCoef(s, o, s, o);
    #pragma unroll
    for (int p = 0; p < 8; p++) {
        u64 px = __shfl_xor_sync(0xffffffffu, AX[p], LM);
        u64 py = __shfl_xor_sync(0xffffffffu, AY[p], LM);
        cupd(AX[p], AY[p], px, py, C, AX[p], AY[p]);
    }
}

// ---------------------------------------------------------------------------
// Fused kernel. Blocks 0..3: one basis column each (256 thr, 16 amps/thread).
// Blocks 4..: wait, build 4x4 Gram, emit 256 outputs each.
// ---------------------------------------------------------------------------
__global__ __launch_bounds__(256, 1) void fused_kernel(
    const float* __restrict__ weights, const float* __restrict__ head_w,
    const float* __restrict__ head_b, const float* __restrict__ sb,
    float* __restrict__ out, int B, int nOut)
{
    extern __shared__ char smem_raw[];
    const int t = threadIdx.x;
    const int bid = blockIdx.x;

    if (bid < 4) {
        // ================= SIM BLOCK =================
        SimSmem* sm = (SimSmem*)smem_raw;
        if (t < 96) {
            float phi = weights[t * 3 + 0];
            float th  = weights[t * 3 + 1];
            float om  = weights[t * 3 + 2];
            float st, ct; sincosf(th * 0.5f, &st, &ct);
            float sp, cp; sincosf((phi + om) * 0.5f, &sp, &cp);
            float sd, cd; sincosf((phi - om) * 0.5f, &sd, &cd);
            sm->rot[t][0] = make_float2( cp * ct, -sp * ct);   // u00
            sm->rot[t][1] = make_float2(-cd * st, -sd * st);   // u01
            sm->rot[t][2] = make_float2( cd * st, -sd * st);   // u10
            sm->rot[t][3] = make_float2( cp * ct,  sp * ct);   // u11
        }
        __syncthreads();

        // init |kj>: bit11 = b0 -> t7, bit10 = b1 -> t6; p=0, pack lane 0
        const int t_init = ((bid >> 1) & 1) * 128 + (bid & 1) * 64;
        u64 AX[8], AY[8];
        #pragma unroll
        for (int p = 0; p < 8; p++) { AX[p] = 0ull; AY[p] = 0ull; }
        if (t == t_init) AX[0] = pack2(1.0f, 0.0f);

        // layer-invariant addresses
        const int baseA = (((t >> 5) & 7) << 8) | (t & 31);   // u64 slot, + p'<<5
        const int base3 = addr3(t << 4);                      // float addr, ^ addr3(l)
        float* fbX = (float*)sm->bX;
        float* fbY = (float*)sm->bY;

        #pragma unroll 1
        for (int l = 0; l < 8; l++) {
            const float2 (*R)[4] = (const float2 (*)[4]) & sm->rot[l * 12];
            // ---- phase 1: wires 11..3 on bits 0..8 ----
            gate_regM<1>(AX, AY, R[11]);        // bit 0
            gate_regM<2>(AX, AY, R[10]);        // bit 1
            gate_regM<4>(AX, AY, R[9]);         // bit 2
            gate_pack  (AX, AY, R[8]);          // bit 3 (pack lane)
            gate_lane<1, 0>(AX, AY, R[7], t);   // bit 4
            gate_lane<2, 1>(AX, AY, R[6], t);   // bit 5
            gate_lane<4, 2>(AX, AY, R[5], t);   // bit 6
            gate_lane<8, 3>(AX, AY, R[4], t);   // bit 7
            gate_lane<16, 4>(AX, AY, R[3], t);  // bit 8
            // ---- transpose: swap bits {0,1,2} <-> {9,10,11} via buffer A ----
            #pragma unroll
            for (int p = 0; p < 8; p++) {
                sm->aX[(p << 8) | t] = AX[p];
                sm->aY[(p << 8) | t] = AY[p];
            }
            __syncthreads();
            #pragma unroll
            for (int p = 0; p < 8; p++) {
                AX[p] = sm->aX[baseA + (p << 5)];
                AY[p] = sm->aY[baseA + (p << 5)];
            }
            // wires 2,1,0 now on bits 0,1,2
            gate_regM<1>(AX, AY, R[2]);
            gate_regM<2>(AX, AY, R[1]);
            gate_regM<4>(AX, AY, R[0]);
            // ---- untranspose + CNOT cascade perm, fused, via buffer B ----
            #pragma unroll
            for (int p = 0; p < 8; p++) {
                sm->bX[(p << 8) | t] = AX[p];
                sm->bY[(p << 8) | t] = AY[p];
            }
            __syncthreads();
            #pragma unroll
            for (int p = 0; p < 8; p++) {
                int a0 = base3 ^ addr3(p);        // pack lane 0 (y3=0)
                int a1 = base3 ^ addr3(8 | p);    // pack lane 1 (y3=1)
                AX[p] = pack2(fbX[a0], fbX[a1]);
                AY[p] = pack2(fbY[a0], fbY[a1]);
            }
        }

        // write column (natural order): amp y = (t<<4) | (lam<<3) | p
        #pragma unroll
        for (int p = 0; p < 8; p++) {
            float2 xs = unpack2(AX[p]), ys = unpack2(AY[p]);
            g_v[bid][(t << 4) | p]     = make_float2(xs.x, ys.x);
            g_v[bid][(t << 4) | 8 | p] = make_float2(xs.y, ys.y);
        }
        __threadfence();
        __syncthreads();
        if (t == 0) atomicAdd(&g_flag, 1);
    } else {
        // ================= OUTPUT BLOCK =================
        // prefetch per-sample data + sincos BEFORE the spin
        const int i = (bid - 4) * 256 + t;
        float s0 = 0.f, c0 = 1.f, s1 = 0.f, c1 = 1.f, hb = head_b[0];
        if (i < B) {
            float t0 = sb[i * 8 + 0], t1 = sb[i * 8 + 1];
            sincosf(t0 * 0.5f, &s0, &c0);
            sincosf(t1 * 0.5f, &s1, &c1);
        }
        float hw[12];
        #pragma unroll
        for (int w = 0; w < 12; w++) hw[w] = head_w[w];

        if (t == 0) {
            while (atomicAdd(&g_flag, 0) < 4) __nanosleep(64);
        }
        __syncthreads();
        __threadfence();

        // --- Gram: G[j][k] = sum_idx s(idx) v_j conj(v_k) ---
        float2 acc[4][4];
        #pragma unroll
        for (int a = 0; a < 4; a++)
            #pragma unroll
            for (int b = 0; b < 4; b++) acc[a][b] = make_float2(0.f, 0.f);

        for (int idx = t; idx < 4096; idx += 256) {
            float s = 0.f;
            #pragma unroll
            for (int w = 0; w < 12; w++)
                s += ((idx >> (11 - w)) & 1) ? -hw[w] : hw[w];
            float2 v[4];
            #pragma unroll
            for (int a = 0; a < 4; a++) v[a] = g_v[a][idx];
            #pragma unroll
            for (int a = 0; a < 4; a++)
                #pragma unroll
                for (int b = 0; b < 4; b++) {
                    float pr = v[a].x * v[b].x + v[a].y * v[b].y;
                    float pi = v[a].y * v[b].x - v[a].x * v[b].y;
                    acc[a][b].x += s * pr;
                    acc[a][b].y += s * pi;
                }
        }

        float* red = (float*)smem_raw;      // [8][32]
        float* Gs  = red + 8 * 32;          // [32]
        float* flat = reinterpret_cast<float*>(acc);
        const int lane = t & 31, warp = t >> 5;
        #pragma unroll
        for (int comp = 0; comp < 32; comp++) {
            float v = flat[comp];
            #pragma unroll
            for (int off = 16; off; off >>= 1)
                v += __shfl_down_sync(0xffffffff, v, off);
            if (lane == 0) red[warp * 32 + comp] = v;
        }
        __syncthreads();
        if (t < 32) {
            float v = 0.f;
            #pragma unroll
            for (int w = 0; w < 8; w++) v += red[w * 32 + t];
            Gs[t] = v;
        }
        __syncthreads();

        // self-resetting flags for graph replays
        if (t == 0) {
            int d = atomicAdd(&g_done2, 1);
            if (d == nOut - 1) { atomicExch(&g_flag, 0); atomicExch(&g_done2, 0); }
        }

        // --- per-sample output: out = Re(c^H G c) + bias ---
        if (i < B) {
            float2 c[4];
            c[0] = make_float2(c0 * c1, 0.f);
            c[1] = make_float2(c0 * s1, 0.f);
            c[2] = make_float2(0.f, -s0 * c1);
            c[3] = make_float2(0.f, -s0 * s1);

            float res = hb;
            #pragma unroll
            for (int jj = 0; jj < 4; jj++)
                #pragma unroll
                for (int k = 0; k < 4; k++) {
                    float ccr = c[jj].x * c[k].x + c[jj].y * c[k].y;
                    float cci = c[jj].y * c[k].x - c[jj].x * c[k].y;
                    float gx = Gs[(jj * 4 + k) * 2];
                    float gy = Gs[(jj * 4 + k) * 2 + 1];
                    res += ccr * gx - cci * gy;
                }
            out[i] = res;
        }
    }
}

extern "C" void kernel_launch(void* const* d_in, const int* in_sizes, int n_in,
                              void* d_out, int out_size) {
    const float* state_batch = (const float*)d_in[0];  // (B, 8)
    const float* weights     = (const float*)d_in[1];  // (8, 12, 3)
    const float* head_w      = (const float*)d_in[2];  // (1, 12)
    const float* head_b      = (const float*)d_in[3];  // (1,)
    float* out = (float*)d_out;
    const int B = in_sizes[0] / 8;

    const int smem_bytes = (int)sizeof(SimSmem);
    cudaFuncSetAttribute(fused_kernel, cudaFuncAttributeMaxDynamicSharedMemorySize,
                         smem_bytes);
    const int nOut = (B + 255) / 256;
    fused_kernel<<<4 + nOut, 256, smem_bytes>>>(weights, head_w, head_b,
                                                state_batch, out, B, nOut);
}

// round 7
// speedup vs baseline: 1.1170x; 1.0009x over previous
#include <cuda_runtime.h>
#include <cuda_bf16.h>

typedef unsigned long long u64;

// Cross-block scratch (no allocations allowed -> __device__ globals)
__device__ float2 g_v[4][4096];   // 4 columns of the circuit unitary (natural order)
__device__ int g_flag = 0;        // sim-columns-done counter (self-resetting)
__device__ int g_done2 = 0;       // output-blocks-passed-spin counter

// ---------------- f32x2 packed helpers ----------------
__device__ __forceinline__ u64 pack2(float x, float y) {
    u64 u; asm("mov.b64 %0, {%1,%2};" : "=l"(u) : "f"(x), "f"(y)); return u;
}
__device__ __forceinline__ float2 unpack2(u64 u) {
    float2 v; asm("mov.b64 {%0,%1}, %2;" : "=f"(v.x), "=f"(v.y) : "l"(u)); return v;
}
__device__ __forceinline__ u64 swap2(u64 u) {
    float2 v = unpack2(u); return pack2(v.y, v.x);
}
__device__ __forceinline__ u64 fma2(u64 a, u64 b, u64 c) {
    u64 d; asm("fma.rn.f32x2 %0, %1, %2, %3;" : "=l"(d) : "l"(a), "l"(b), "l"(c)); return d;
}
__device__ __forceinline__ u64 mul2(u64 a, u64 b) {
    u64 d; asm("mul.rn.f32x2 %0, %1, %2;" : "=l"(d) : "l"(a), "l"(b)); return d;
}

struct Coef { u64 sx, sy, nsy, ox, oy, noy; };

__device__ __forceinline__ Coef makeCoef(float2 s0, float2 o0, float2 s1, float2 o1) {
    Coef c;
    c.sx  = pack2(s0.x, s1.x);
    c.sy  = pack2(s0.y, s1.y);
    c.nsy = pack2(-s0.y, -s1.y);
    c.ox  = pack2(o0.x, o1.x);
    c.oy  = pack2(o0.y, o1.y);
    c.noy = pack2(-o0.y, -o1.y);
    return c;
}

// new = s*a + o*p (complex, 2 packed lanes): 8 f32x2 ops
__device__ __forceinline__ void cupd(u64 X, u64 Y, u64 PX, u64 PY, const Coef& c,
                                     u64& NX, u64& NY) {
    u64 nx = mul2(c.sx, X);
    nx = fma2(c.nsy, Y, nx);
    nx = fma2(c.ox, PX, nx);
    nx = fma2(c.noy, PY, nx);
    u64 ny = mul2(c.sx, Y);
    ny = fma2(c.sy, X, ny);
    ny = fma2(c.ox, PY, ny);
    ny = fma2(c.oy, PX, ny);
    NX = nx; NY = ny;
}

// ---------------- shared memory (dynamic, ~67KB) ----------------
struct SimSmem {
    float2 rot[96][4];              // u00,u01,u10,u11 per gate
    u64 aX[2048]; u64 aY[2048];     // staging A (transpose)
    u64 bX[2048]; u64 bY[2048];     // staging B (untranspose + wire3 + CNOT perm)
};

// ---------------------------------------------------------------------------
// Indexing (512 threads, 8 amps/thread).
// Amp x (12 bits): x0,x1 = pair p; x2 = pack lane lam (f32x2); x3..x7 = lane
// bits t0..t4; x8..x11 = warp bits t5..t8. Wire w acts on bit 11-w.
// sigma swaps bits {0,1,2} <-> {9,10,11}; bit 8 (wire 3) is fused into the
// phase-3 gather (single-qubit gates on distinct wires commute).
// Staging float addr (natural): fnat(x) = x2 | (x3..x11 << 1) | (x0x1 << 10),
// then swizzle: fsw(f) = f ^ ((f>>5)&1)  (makes every pattern bank-bijective).
// All maps are GF(2)-linear -> addr(base ^ delta) = addr(base) ^ addr(delta).
// ---------------------------------------------------------------------------
__host__ __device__ constexpr int fnat(int x) {
    return ((x >> 2) & 1) | (((x >> 3) & 0x1FF) << 1) | ((x & 3) << 10);
}
__host__ __device__ constexpr int sig(int z) {
    return (z & 0x1F8) | ((z & 7) << 9) | ((z >> 9) & 7);
}
__host__ __device__ constexpr int fsw(int f) { return f ^ ((f >> 5) & 1); }
__host__ __device__ constexpr int A2f(int z) { return fsw(fnat(sig(z))); }
__host__ __device__ constexpr int A3f(int y) {
    return fsw(fnat(sig((y ^ (y >> 1)) & 0xFFF)));
}

// gate on pair bit M (in-register partner A[p^M])
template<int M>
__device__ __forceinline__ void gate_regM(u64 AX[4], u64 AY[4], const float2* u) {
    Coef C0 = makeCoef(u[0], u[1], u[0], u[1]);
    Coef C1 = makeCoef(u[3], u[2], u[3], u[2]);
    #pragma unroll
    for (int p = 0; p < 4; p++) {
        if (p & M) continue;
        int q = p | M;
        u64 x0 = AX[p], y0 = AY[p], x1 = AX[q], y1 = AY[q];
        cupd(x0, y0, x1, y1, C0, AX[p], AY[p]);
        cupd(x1, y1, x0, y0, C1, AX[q], AY[q]);
    }
}

// gate on the pack bit (partner = other f32x2 lane)
__device__ __forceinline__ void gate_pack(u64 AX[4], u64 AY[4], const float2* u) {
    Coef C = makeCoef(u[0], u[1], u[3], u[2]);
    #pragma unroll
    for (int p = 0; p < 4; p++) {
        u64 px = swap2(AX[p]), py = swap2(AY[p]);
        cupd(AX[p], AY[p], px, py, C, AX[p], AY[p]);
    }
}

// gate on lane bit K (shfl partner lane t ^ LM)
template<int LM, int K>
__device__ __forceinline__ void gate_lane(u64 AX[4], u64 AY[4], const float2* u, int t) {
    const bool pt = (t >> K) & 1;
    float2 s = pt ? u[3] : u[0];
    float2 o = pt ? u[2] : u[1];
    Coef C = makeCoef(s, o, s, o);
    #pragma unroll
    for (int p = 0; p < 4; p++) {
        u64 px = __shfl_xor_sync(0xffffffffu, AX[p], LM);
        u64 py = __shfl_xor_sync(0xffffffffu, AY[p], LM);
        cupd(AX[p], AY[p], px, py, C, AX[p], AY[p]);
    }
}

// ---------------------------------------------------------------------------
// Fused kernel. Blocks 0..3: one basis column each (512 thr, 8 amps/thread).
// Blocks 4..: wait, build 4x4 Gram, emit 512 outputs each.
// ---------------------------------------------------------------------------
__global__ __launch_bounds__(512, 1) void fused_kernel(
    const float* __restrict__ weights, const float* __restrict__ head_w,
    const float* __restrict__ head_b, const float* __restrict__ sb,
    float* __restrict__ out, int B, int nOut)
{
    extern __shared__ char smem_raw[];
    const int t = threadIdx.x;
    const int bid = blockIdx.x;

    if (bid < 4) {
        // ================= SIM BLOCK =================
        SimSmem* sm = (SimSmem*)smem_raw;
        if (t < 96) {
            float phi = weights[t * 3 + 0];
            float th  = weights[t * 3 + 1];
            float om  = weights[t * 3 + 2];
            float st, ct; sincosf(th * 0.5f, &st, &ct);
            float sp, cp; sincosf((phi + om) * 0.5f, &sp, &cp);
            float sd, cd; sincosf((phi - om) * 0.5f, &sd, &cd);
            sm->rot[t][0] = make_float2( cp * ct, -sp * ct);   // u00
            sm->rot[t][1] = make_float2(-cd * st, -sd * st);   // u01
            sm->rot[t][2] = make_float2( cd * st, -sd * st);   // u10
            sm->rot[t][3] = make_float2( cp * ct,  sp * ct);   // u11
        }
        __syncthreads();

        // init |kj>: bit11 = b0 -> t8, bit10 = b1 -> t7; p=0, lam=0
        const int t_init = ((bid >> 1) & 1) * 256 + (bid & 1) * 128;
        u64 AX[4], AY[4];
        #pragma unroll
        for (int p = 0; p < 4; p++) { AX[p] = 0ull; AY[p] = 0ull; }
        if (t == t_init) AX[0] = pack2(1.0f, 0.0f);

        // layer-invariant addresses (all swizzled float slots)
        const int storeBase = (t << 1) ^ ((t >> 4) & 1);         // ^lam ^(p<<10)
        const int base2 = A2f(t << 3);                           // ^cA2[p] ^A2L
        const int base3 = A3f(t << 3);                           // ^cA3[p] ^A3L
        constexpr int cA2[4] = { A2f(0), A2f(1), A2f(2), A2f(3) };
        constexpr int A2L = A2f(4);
        constexpr int cA3[4] = { A3f(0), A3f(1), A3f(2), A3f(3) };
        constexpr int A3L = A3f(4);
        float* fAX = (float*)sm->aX; float* fAY = (float*)sm->aY;
        float* fBX = (float*)sm->bX; float* fBY = (float*)sm->bY;

        #pragma unroll 1
        for (int l = 0; l < 8; l++) {
            const float2 (*R)[4] = (const float2 (*)[4]) & sm->rot[l * 12];
            // ---- phase 1: wires 11..4 on bits 0..7 ----
            gate_regM<1>(AX, AY, R[11]);        // bit 0
            gate_regM<2>(AX, AY, R[10]);        // bit 1
            gate_pack  (AX, AY, R[9]);          // bit 2 (pack lane)
            gate_lane<1, 0>(AX, AY, R[8], t);   // bit 3
            gate_lane<2, 1>(AX, AY, R[7], t);   // bit 4
            gate_lane<4, 2>(AX, AY, R[6], t);   // bit 5
            gate_lane<8, 3>(AX, AY, R[5], t);   // bit 6
            gate_lane<16, 4>(AX, AY, R[4], t);  // bit 7
            // ---- transpose: swap bits {0,1,2} <-> {9,10,11} via buffer A ----
            #pragma unroll
            for (int p = 0; p < 4; p++) {
                float2 xs = unpack2(AX[p]), ys = unpack2(AY[p]);
                int a0 = storeBase ^ (p << 10);
                fAX[a0] = xs.x; fAX[a0 ^ 1] = xs.y;
                fAY[a0] = ys.x; fAY[a0 ^ 1] = ys.y;
            }
            __syncthreads();
            #pragma unroll
            for (int p = 0; p < 4; p++) {
                int a0 = base2 ^ cA2[p];
                AX[p] = pack2(fAX[a0], fAX[a0 ^ A2L]);
                AY[p] = pack2(fAY[a0], fAY[a0 ^ A2L]);
            }
            // wires 2,1,0 now on bits 0,1,2
            gate_regM<1>(AX, AY, R[2]);
            gate_regM<2>(AX, AY, R[1]);
            gate_pack  (AX, AY, R[0]);
            // ---- phase 3: untranspose + wire-3 gate + CNOT perm via buffer B ----
            #pragma unroll
            for (int p = 0; p < 4; p++) {
                float2 xs = unpack2(AX[p]), ys = unpack2(AY[p]);
                int a0 = storeBase ^ (p << 10);
                fBX[a0] = xs.x; fBX[a0 ^ 1] = xs.y;
                fBY[a0] = ys.x; fBY[a0 ^ 1] = ys.y;
            }
            __syncthreads();
            {
                // wire-3 gate (natural bit 8): branch = g8 = y8^y9 = t5^t6
                const bool b8 = ((t >> 5) ^ (t >> 6)) & 1;
                float2 s = b8 ? R[3][3] : R[3][0];
                float2 o = b8 ? R[3][2] : R[3][1];
                Coef C = makeCoef(s, o, s, o);
                #pragma unroll
                for (int p = 0; p < 4; p++) {
                    int a0 = base3 ^ cA3[p];
                    int a1 = a0 ^ A3L;
                    u64 VX = pack2(fBX[a0], fBX[a1]);
                    u64 VY = pack2(fBY[a0], fBY[a1]);
                    u64 PX = pack2(fBX[a0 ^ 64], fBX[a1 ^ 64]);
                    u64 PY = pack2(fBY[a0 ^ 64], fBY[a1 ^ 64]);
                    cupd(VX, VY, PX, PY, C, AX[p], AY[p]);
                }
            }
        }

        // write column (natural order): amp y = (t<<3) | (lam<<2) | p
        #pragma unroll
        for (int p = 0; p < 4; p++) {
            float2 xs = unpack2(AX[p]), ys = unpack2(AY[p]);
            g_v[bid][(t << 3) | p]     = make_float2(xs.x, ys.x);
            g_v[bid][(t << 3) | 4 | p] = make_float2(xs.y, ys.y);
        }
        __threadfence();
        __syncthreads();
        if (t == 0) atomicAdd(&g_flag, 1);
    } else {
        // ================= OUTPUT BLOCK =================
        // prefetch per-sample data + sincos BEFORE the spin
        const int i = (bid - 4) * 512 + t;
        float s0 = 0.f, c0 = 1.f, s1 = 0.f, c1 = 1.f, hb = head_b[0];
        if (i < B) {
            float t0 = sb[i * 8 + 0], t1 = sb[i * 8 + 1];
            sincosf(t0 * 0.5f, &s0, &c0);
            sincosf(t1 * 0.5f, &s1, &c1);
        }
        float hw[12];
        #pragma unroll
        for (int w = 0; w < 12; w++) hw[w] = head_w[w];

        if (t == 0) {
            while (atomicAdd(&g_flag, 0) < 4) __nanosleep(64);
        }
        __syncthreads();
        __threadfence();

        // --- Gram: G[j][k] = sum_idx s(idx) v_j conj(v_k) ---
        float2 acc[4][4];
        #pragma unroll
        for (int a = 0; a < 4; a++)
            #pragma unroll
            for (int b = 0; b < 4; b++) acc[a][b] = make_float2(0.f, 0.f);

        for (int idx = t; idx < 4096; idx += 512) {
            float s = 0.f;
            #pragma unroll
            for (int w = 0; w < 12; w++)
                s += ((idx >> (11 - w)) & 1) ? -hw[w] : hw[w];
            float2 v[4];
            #pragma unroll
            for (int a = 0; a < 4; a++) v[a] = g_v[a][idx];
            #pragma unroll
            for (int a = 0; a < 4; a++)
                #pragma unroll
                for (int b = 0; b < 4; b++) {
                    float pr = v[a].x * v[b].x + v[a].y * v[b].y;
                    float pi = v[a].y * v[b].x - v[a].x * v[b].y;
                    acc[a][b].x += s * pr;
                    acc[a][b].y += s * pi;
                }
        }

        float* red = (float*)smem_raw;      // [16][32]
        float* Gs  = red + 16 * 32;         // [32]
        float* flat = reinterpret_cast<float*>(acc);
        const int lane = t & 31, warp = t >> 5;
        #pragma unroll
        for (int comp = 0; comp < 32; comp++) {
            float v = flat[comp];
            #pragma unroll
            for (int off = 16; off; off >>= 1)
                v += __shfl_down_sync(0xffffffff, v, off);
            if (lane == 0) red[warp * 32 + comp] = v;
        }
        __syncthreads();
        if (t < 32) {
            float v = 0.f;
            #pragma unroll
            for (int w = 0; w < 16; w++) v += red[w * 32 + t];
            Gs[t] = v;
        }
        __syncthreads();

        // self-resetting flags for graph replays
        if (t == 0) {
            int d = atomicAdd(&g_done2, 1);
            if (d == nOut - 1) { atomicExch(&g_flag, 0); atomicExch(&g_done2, 0); }
        }

        // --- per-sample output: out = Re(c^H G c) + bias ---
        if (i < B) {
            float2 c[4];
            c[0] = make_float2(c0 * c1, 0.f);
            c[1] = make_float2(c0 * s1, 0.f);
            c[2] = make_float2(0.f, -s0 * c1);
            c[3] = make_float2(0.f, -s0 * s1);

            float res = hb;
            #pragma unroll
            for (int jj = 0; jj < 4; jj++)
                #pragma unroll
                for (int k = 0; k < 4; k++) {
                    float ccr = c[jj].x * c[k].x + c[jj].y * c[k].y;
                    float cci = c[jj].y * c[k].x - c[jj].x * c[k].y;
                    float gx = Gs[(jj * 4 + k) * 2];
                    float gy = Gs[(jj * 4 + k) * 2 + 1];
                    res += ccr * gx - cci * gy;
                }
            out[i] = res;
        }
    }
}

extern "C" void kernel_launch(void* const* d_in, const int* in_sizes, int n_in,
                              void* d_out, int out_size) {
    const float* state_batch = (const float*)d_in[0];  // (B, 8)
    const float* weights     = (const float*)d_in[1];  // (8, 12, 3)
    const float* head_w      = (const float*)d_in[2];  // (1, 12)
    const float* head_b      = (const float*)d_in[3];  // (1,)
    float* out = (float*)d_out;
    const int B = in_sizes[0] / 8;

    const int smem_bytes = (int)sizeof(SimSmem);
    cudaFuncSetAttribute(fused_kernel, cudaFuncAttributeMaxDynamicSharedMemorySize,
                         smem_bytes);
    const int nOut = (B + 511) / 512;
    fused_kernel<<<4 + nOut, 512, smem_bytes>>>(weights, head_w, head_b,
                                                state_batch, out, B, nOut);
}